// round 3
// baseline (speedup 1.0000x reference)
#include <cuda_runtime.h>
#include <math.h>

// Problem constants
#define BATCH      8192
#define PIECES     32
#define NNZ        (BATCH * PIECES)      // 262144
#define NFEAT      768
#define FTOUT      512
#define NSLICE     8
#define SCOLS      64                    // FTOUT / NSLICE
#define WSTRIDE    68                    // padded smem row stride (floats), 16B aligned, conflict-free
#define ROWS_ITER  32                    // batch rows per iteration
#define ITERS_TOT  (BATCH / ROWS_ITER)   // 256
#define BLOCKS_X   19                    // 19 * 8 slices = 152 blocks = #SMs on GB300
#define THREADS    512
#define IDXSTRIDE  33                    // padded staging stride to dodge broadcast bank aliasing

// shared memory layout (float indices)
#define OFF_W      0
#define OFF_STM    (NFEAT * WSTRIDE)                     // 52224
#define OFF_NSTM   (OFF_STM + ROWS_ITER * IDXSTRIDE)     // 53280
#define OFF_VAL    (OFF_NSTM + ROWS_ITER * IDXSTRIDE)    // 54336
#define SM_FLOATS  (OFF_VAL + ROWS_ITER * IDXSTRIDE)     // 55392
#define SM_BYTES   (SM_FLOATS * 4)                       // 221568 B <= 227KB dyn smem cap

// Deterministic scratch: one writer per (slice, row). No atomics, fully overwritten each launch.
__device__ float g_partial[NSLICE * BATCH];

__device__ __forceinline__ float sat01(float x) { return __saturatef(x); }

__global__ __launch_bounds__(THREADS, 1)
void ft_kernel(const int* __restrict__ stm_idx,     // [2, NNZ] (int32 OR int64 words; see idx64 probe)
               const int* __restrict__ nstm_idx,
               const float* __restrict__ values,    // [NNZ]
               const float* __restrict__ ft_w,      // [768, 512]
               const float* __restrict__ ft_b,      // [512]
               const float* __restrict__ out_w)     // [1024, 1]
{
    extern __shared__ float sm[];
    int* smi = (int*)sm;

    const int tid = threadIdx.x;
    const int s   = blockIdx.y;          // column slice 0..7

    // Runtime dtype probe: row 0 = repeat(arange(8192),32). Under int32 layout,
    // word NNZ-1 == 8191 (last batch id). Under int64 layout, word NNZ-1 is the
    // high half of element 131071 == 0. Uniform per-block branch; hot loop unaffected.
    const bool idx64 = (stm_idx[NNZ - 1] != 8191);

    // ---- Load ft_w column slice [768 x 64] into smem (stride-68 rows) ----
    for (int i = tid; i < NFEAT * (SCOLS / 4); i += THREADS) {
        const int f  = i >> 4;           // feature row
        const int c4 = i & 15;           // float4 within slice
        const float4 w = *(const float4*)(ft_w + f * FTOUT + s * SCOLS + c4 * 4);
        *(float4*)(sm + OFF_W + f * WSTRIDE + c4 * 4) = w;
    }

    // ---- Per-thread constants ----
    const int q  = tid & 15;             // float4-group within slice (cols q*4..q*4+3)
    const int rl = tid >> 4;             // local row 0..31
    const float4 ftb = *(const float4*)(ft_b + s * SCOLS + q * 4);
    const float4 owS = *(const float4*)(out_w + s * SCOLS + q * 4);
    const float4 owN = *(const float4*)(out_w + FTOUT + s * SCOLS + q * 4);
    const int q4 = q * 4;

    __syncthreads();

    // ---- Persistent loop over row-iterations (strided across the 19 x-blocks) ----
    for (int it = blockIdx.x; it < ITERS_TOT; it += BLOCKS_X) {
        const int rbase = it * ROWS_ITER;
        const int n0 = rbase * PIECES;   // nnz offset, multiple of 1024

        // Stage 32 rows x 32 indices (pre-multiplied by WSTRIDE) + values into smem
        if (tid < (ROWS_ITER * PIECES) / 4) {
            const int i = tid;                  // 0..255, 4 elements each
            int ax, ay, az, aw, bx, by, bz, bw;
            if (!idx64) {
                // feature row lives at word offset NNZ
                const int4 a = *(const int4*)(stm_idx  + NNZ + n0 + i * 4);
                const int4 b = *(const int4*)(nstm_idx + NNZ + n0 + i * 4);
                ax = a.x; ay = a.y; az = a.z; aw = a.w;
                bx = b.x; by = b.y; bz = b.z; bw = b.w;
            } else {
                // int64 layout: feature row at word offset 2*NNZ, 2 words/element (little-endian lo first)
                const long e = 2L * NNZ + 2L * (n0 + i * 4);
                const int4 a0 = *(const int4*)(stm_idx  + e);
                const int4 a1 = *(const int4*)(stm_idx  + e + 4);
                const int4 b0 = *(const int4*)(nstm_idx + e);
                const int4 b1 = *(const int4*)(nstm_idx + e + 4);
                ax = a0.x; ay = a0.z; az = a1.x; aw = a1.z;
                bx = b0.x; by = b0.z; bz = b1.x; bw = b1.z;
            }
            const float4 v = *(const float4*)(values + n0 + i * 4);
            const int row = i >> 3;
            const int pp  = (i & 7) * 4;
            const int d   = row * IDXSTRIDE + pp;
            smi[OFF_STM + d + 0] = ax * WSTRIDE;
            smi[OFF_STM + d + 1] = ay * WSTRIDE;
            smi[OFF_STM + d + 2] = az * WSTRIDE;
            smi[OFF_STM + d + 3] = aw * WSTRIDE;
            smi[OFF_NSTM + d + 0] = bx * WSTRIDE;
            smi[OFF_NSTM + d + 1] = by * WSTRIDE;
            smi[OFF_NSTM + d + 2] = bz * WSTRIDE;
            smi[OFF_NSTM + d + 3] = bw * WSTRIDE;
            sm[OFF_VAL + d + 0] = v.x;
            sm[OFF_VAL + d + 1] = v.y;
            sm[OFF_VAL + d + 2] = v.z;
            sm[OFF_VAL + d + 3] = v.w;
        }
        __syncthreads();

        // ---- Accumulate this thread's 4 columns for one batch row ----
        float4 aS = ftb;
        float4 aN = ftb;
        const int base = rl * IDXSTRIDE;
        #pragma unroll
        for (int p = 0; p < PIECES; p++) {
            const int   fS = smi[OFF_STM  + base + p];   // already *WSTRIDE
            const int   fN = smi[OFF_NSTM + base + p];
            const float v  = sm [OFF_VAL  + base + p];
            const float4 wS = *(const float4*)(sm + fS + q4);
            const float4 wN = *(const float4*)(sm + fN + q4);
            aS.x = fmaf(v, wS.x, aS.x);
            aS.y = fmaf(v, wS.y, aS.y);
            aS.z = fmaf(v, wS.z, aS.z);
            aS.w = fmaf(v, wS.w, aS.w);
            aN.x = fmaf(v, wN.x, aN.x);
            aN.y = fmaf(v, wN.y, aN.y);
            aN.z = fmaf(v, wN.z, aN.z);
            aN.w = fmaf(v, wN.w, aN.w);
        }

        // clip(0,1) then dot with out_w slice
        float partial =
            sat01(aS.x) * owS.x + sat01(aS.y) * owS.y +
            sat01(aS.z) * owS.z + sat01(aS.w) * owS.w +
            sat01(aN.x) * owN.x + sat01(aN.y) * owN.y +
            sat01(aN.z) * owN.z + sat01(aN.w) * owN.w;

        // reduce across the 16 lanes covering this row's 64 columns
        #pragma unroll
        for (int off = 8; off > 0; off >>= 1)
            partial += __shfl_xor_sync(0xffffffffu, partial, off, 16);

        if (q == 0)
            g_partial[s * BATCH + rbase + rl] = partial;

        __syncthreads();   // protect staging buffers before next iteration
    }
}

__global__ void out_kernel(const float* __restrict__ out_b, float* __restrict__ out)
{
    const int b = blockIdx.x * blockDim.x + threadIdx.x;
    if (b < BATCH) {
        float x = out_b[0];
        #pragma unroll
        for (int s = 0; s < NSLICE; s++)
            x += g_partial[s * BATCH + b];
        out[b] = 1.0f / (1.0f + expf(-x));
    }
}

extern "C" void kernel_launch(void* const* d_in, const int* in_sizes, int n_in,
                              void* d_out, int out_size)
{
    (void)in_sizes; (void)n_in; (void)out_size;
    const int*   stm_idx  = (const int*)  d_in[0];  // [2, NNZ]
    const int*   nstm_idx = (const int*)  d_in[1];  // [2, NNZ]
    const float* values   = (const float*)d_in[2];  // [NNZ]
    const float* ft_w     = (const float*)d_in[3];  // [768, 512]
    const float* ft_b     = (const float*)d_in[4];  // [512]
    const float* out_w    = (const float*)d_in[5];  // [1024, 1]
    const float* out_b    = (const float*)d_in[6];  // [1]
    // d_in[7] = batch_size (unused; compile-time constant)
    float* out = (float*)d_out;

    cudaFuncSetAttribute(ft_kernel, cudaFuncAttributeMaxDynamicSharedMemorySize, SM_BYTES);

    dim3 grid(BLOCKS_X, NSLICE);
    ft_kernel<<<grid, THREADS, SM_BYTES>>>(stm_idx, nstm_idx, values, ft_w, ft_b, out_w);
    out_kernel<<<(BATCH + 255) / 256, 256>>>(out_b, out);
}

// round 7
// speedup vs baseline: 1.0006x; 1.0006x over previous
#include <cuda_runtime.h>
#include <math.h>

// Problem constants
#define BATCH      8192
#define PIECES     32
#define NNZ        (BATCH * PIECES)      // 262144
#define NFEAT      768
#define FTOUT      512
#define NSLICE     8
#define SCOLS      64                    // FTOUT / NSLICE
#define WSTRIDE    68                    // padded smem row stride (floats): conflict-free gathers
#define ROWS_ITER  32                    // batch rows per iteration
#define ITERS_TOT  (BATCH / ROWS_ITER)   // 256
#define BLOCKS_X   19                    // 19 * 8 slices = 152 blocks = #SMs
#define THREADS    512
#define IDX4STRIDE 33                    // staging stride in int4 units (132 words: +4 banks/row)

// shared memory layout
#define OFF_W       0                    // float index
#define OFF_IDX4    13056                // int4 index (= 52224 floats / 4), entries after weights
#define SM_BYTES    ((OFF_IDX4 + ROWS_ITER * IDX4STRIDE) * 16)   // 225792 B <= 227KB cap

// Deterministic scratch, transposed [batch][slice]: one writer per element.
__device__ float g_partial[BATCH * NSLICE];

__device__ __forceinline__ float sat01(float x) { return __saturatef(x); }

__device__ __forceinline__ void ffma2(unsigned long long& acc, unsigned long long w,
                                      unsigned long long vv) {
    asm("fma.rn.f32x2 %0, %1, %2, %3;" : "=l"(acc) : "l"(w), "l"(vv), "l"(acc));
}
__device__ __forceinline__ unsigned long long packf2(float lo, float hi) {
    unsigned long long r;
    asm("mov.b64 %0, {%1, %2};" : "=l"(r) : "f"(lo), "f"(hi));
    return r;
}
__device__ __forceinline__ void unpackf2(float& lo, float& hi, unsigned long long v) {
    asm("mov.b64 {%0, %1}, %2;" : "=f"(lo), "=f"(hi) : "l"(v));
}

__global__ __launch_bounds__(THREADS, 1)
void ft_kernel(const int* __restrict__ stm_idx,     // [2, NNZ] int32; features at +NNZ
               const int* __restrict__ nstm_idx,
               const float* __restrict__ values,    // [NNZ]
               const float* __restrict__ ft_w,      // [768, 512]
               const float* __restrict__ ft_b,      // [512]
               const float* __restrict__ out_w)     // [1024, 1]
{
    extern __shared__ float sm[];
    int4* smi4 = (int4*)sm;

    const int tid = threadIdx.x;
    const int s   = blockIdx.y;          // column slice 0..7

    // ---- Load ft_w column slice [768 x 64] into smem (stride-68 rows) ----
    for (int i = tid; i < NFEAT * (SCOLS / 4); i += THREADS) {
        const int f  = i >> 4;           // feature row
        const int c4 = i & 15;           // float4 within slice
        const float4 w = *(const float4*)(ft_w + f * FTOUT + s * SCOLS + c4 * 4);
        *(float4*)(sm + OFF_W + f * WSTRIDE + c4 * 4) = w;
    }

    // ---- Per-thread constants ----
    const int q  = tid & 15;             // float4-group within slice (cols q*4..q*4+3)
    const int rl = tid >> 4;             // local row 0..31
    const int q4 = q * 4;
    const float4 ftb = *(const float4*)(ft_b + s * SCOLS + q4);
    const float4 owS = *(const float4*)(out_w + s * SCOLS + q4);
    const float4 owN = *(const float4*)(out_w + FTOUT + s * SCOLS + q4);
    const unsigned long long b01 = packf2(ftb.x, ftb.y);
    const unsigned long long b23 = packf2(ftb.z, ftb.w);

    __syncthreads();

    // ---- Persistent loop over row-iterations (strided across the 19 x-blocks) ----
    for (int it = blockIdx.x; it < ITERS_TOT; it += BLOCKS_X) {
        const int rbase = it * ROWS_ITER;
        const int n0 = rbase * PIECES;   // nnz offset, multiple of 1024

        // Stage packed entries: (fS*68, fN*68, value_bits, 0) per piece, int4 each.
        if (tid < (ROWS_ITER * PIECES) / 4) {
            const int i = tid;                  // 0..255, 4 pieces each
            const int4   a = *(const int4*)(stm_idx  + NNZ + n0 + i * 4);
            const int4   b = *(const int4*)(nstm_idx + NNZ + n0 + i * 4);
            const float4 v = *(const float4*)(values + n0 + i * 4);
            const int row = i >> 3;
            const int d   = OFF_IDX4 + row * IDX4STRIDE + (i & 7) * 4;
            smi4[d + 0] = make_int4(a.x * WSTRIDE, b.x * WSTRIDE, __float_as_int(v.x), 0);
            smi4[d + 1] = make_int4(a.y * WSTRIDE, b.y * WSTRIDE, __float_as_int(v.y), 0);
            smi4[d + 2] = make_int4(a.z * WSTRIDE, b.z * WSTRIDE, __float_as_int(v.z), 0);
            smi4[d + 3] = make_int4(a.w * WSTRIDE, b.w * WSTRIDE, __float_as_int(v.w), 0);
        }
        __syncthreads();

        // ---- Accumulate this thread's 4 columns for one batch row ----
        unsigned long long aS01 = b01, aS23 = b23, aN01 = b01, aN23 = b23;
        const int4* eptr = smi4 + OFF_IDX4 + rl * IDX4STRIDE;
        #pragma unroll
        for (int p = 0; p < PIECES; p++) {
            const int4 e = eptr[p];      // one broadcast LDS.128 per piece
            unsigned long long vv;
            asm("mov.b64 %0, {%1, %1};" : "=l"(vv) : "r"(e.z));
            const ulonglong2 wS = *(const ulonglong2*)(sm + e.x + q4);
            const ulonglong2 wN = *(const ulonglong2*)(sm + e.y + q4);
            ffma2(aS01, wS.x, vv);
            ffma2(aS23, wS.y, vv);
            ffma2(aN01, wN.x, vv);
            ffma2(aN23, wN.y, vv);
        }

        // clip(0,1) then dot with out_w slice
        float sx, sy, sz, sw, nx, ny, nz, nw;
        unpackf2(sx, sy, aS01); unpackf2(sz, sw, aS23);
        unpackf2(nx, ny, aN01); unpackf2(nz, nw, aN23);
        float partial =
            sat01(sx) * owS.x + sat01(sy) * owS.y +
            sat01(sz) * owS.z + sat01(sw) * owS.w +
            sat01(nx) * owN.x + sat01(ny) * owN.y +
            sat01(nz) * owN.z + sat01(nw) * owN.w;

        // reduce across the 16 lanes covering this row's 64 columns
        #pragma unroll
        for (int off = 8; off > 0; off >>= 1)
            partial += __shfl_xor_sync(0xffffffffu, partial, off, 16);

        if (q == 0)
            g_partial[(rbase + rl) * NSLICE + s] = partial;

        __syncthreads();   // protect staging buffers before next iteration
    }
}

__global__ void out_kernel(const float* __restrict__ out_b, float* __restrict__ out)
{
    const int b = blockIdx.x * blockDim.x + threadIdx.x;
    if (b < BATCH) {
        const float4* gp = (const float4*)(g_partial + b * NSLICE);
        const float4 p0 = gp[0];
        const float4 p1 = gp[1];
        const float x = out_b[0] + p0.x + p0.y + p0.z + p0.w
                                 + p1.x + p1.y + p1.z + p1.w;
        out[b] = 1.0f / (1.0f + __expf(-x));
    }
}

extern "C" void kernel_launch(void* const* d_in, const int* in_sizes, int n_in,
                              void* d_out, int out_size)
{
    (void)in_sizes; (void)n_in; (void)out_size;
    const int*   stm_idx  = (const int*)  d_in[0];  // [2, NNZ] int32
    const int*   nstm_idx = (const int*)  d_in[1];  // [2, NNZ] int32
    const float* values   = (const float*)d_in[2];  // [NNZ]
    const float* ft_w     = (const float*)d_in[3];  // [768, 512]
    const float* ft_b     = (const float*)d_in[4];  // [512]
    const float* out_w    = (const float*)d_in[5];  // [1024, 1]
    const float* out_b    = (const float*)d_in[6];  // [1]
    float* out = (float*)d_out;

    cudaFuncSetAttribute(ft_kernel, cudaFuncAttributeMaxDynamicSharedMemorySize, SM_BYTES);

    dim3 grid(BLOCKS_X, NSLICE);
    ft_kernel<<<grid, THREADS, SM_BYTES>>>(stm_idx, nstm_idx, values, ft_w, ft_b, out_w);
    out_kernel<<<(BATCH + 255) / 256, 256>>>(out_b, out);
}